// round 5
// baseline (speedup 1.0000x reference)
#include <cuda_runtime.h>
#include <cstdint>

#define R      128
#define R2     (R * R)
#define R3     (R * R * R)
#define BATCH  2
#define NV     7700
#define NSURF  6890
#define NT     30000

#define SIGMA  0.05f
#define EPS_W  0.001f
#define INV_2SIG2 (1.0f / (2.0f * SIGMA * SIGMA))   // 200.0
#define INV_R  (1.0f / 128.0f)

// Tiling for the gather-splat kernel
#define TILE      8
#define TILES_AX  (R / TILE)                       // 16
#define NTILE_B   (TILES_AX * TILES_AX * TILES_AX) // 4096
#define NTILE     (BATCH * NTILE_B)                // 8192
#define CAP       96                               // max vertices per tile (λ≈9)

// Scratch (no float4 accumulator anymore!)
__device__ unsigned char g_occ[BATCH * R3];        // ~4.2 MB
__device__ int           g_cnt[NTILE];
__device__ int           g_list[NTILE * CAP];      // ~3 MB

// ---------------------------------------------------------------------------
// 1) init: occ = 0 (word-wide), tile counts = 0
// ---------------------------------------------------------------------------
#define OCC_WORDS (BATCH * R3 / 4)
__global__ void init_kernel() {
    int i = blockIdx.x * blockDim.x + threadIdx.x;
    if (i < OCC_WORDS) ((unsigned int*)g_occ)[i] = 0u;
    if (i < NTILE)     g_cnt[i] = 0;
}

// ---------------------------------------------------------------------------
// 2) bin: each surface vertex registers itself with every 8^3 tile its
//    7^3 splat box overlaps (<= 8 tiles).
// ---------------------------------------------------------------------------
__global__ void bin_kernel(const float* __restrict__ verts) {
    int t = blockIdx.x * blockDim.x + threadIdx.x;
    if (t >= BATCH * NSURF) return;
    int b = t / NSURF;
    int s = t - b * NSURF;

    const float* vp = verts + ((size_t)b * NV + s) * 3;
    int bx = (int)floorf(vp[0] * (float)R);
    int by = (int)floorf(vp[1] * (float)R);
    int bz = (int)floorf(vp[2] * (float)R);

    int txs = max(bx - 3, 0) >> 3, txe = min(bx + 3, R - 1) >> 3;
    int tys = max(by - 3, 0) >> 3, tye = min(by + 3, R - 1) >> 3;
    int tzs = max(bz - 3, 0) >> 3, tze = min(bz + 3, R - 1) >> 3;

    for (int tz = tzs; tz <= tze; tz++)
        for (int ty = tys; ty <= tye; ty++)
            for (int tx = txs; tx <= txe; tx++) {
                int tile = b * NTILE_B + (tz * TILES_AX + ty) * TILES_AX + tx;
                int pos = atomicAdd(&g_cnt[tile], 1);
                if (pos < CAP) g_list[tile * CAP + pos] = s;
            }
}

// ---------------------------------------------------------------------------
// 3) tet occupancy: triple-product barycentrics, clamped voxel ranges
// ---------------------------------------------------------------------------
__global__ void tet_kernel(const float* __restrict__ verts,
                           const int*   __restrict__ tets) {
    int t = blockIdx.x * blockDim.x + threadIdx.x;
    if (t >= BATCH * NT) return;
    int b  = t / NT;
    int ti = t - b * NT;

    int i0 = tets[ti * 4 + 0];
    int i1 = tets[ti * 4 + 1];
    int i2 = tets[ti * 4 + 2];
    int i3 = tets[ti * 4 + 3];

    const float* vb = verts + (size_t)b * NV * 3;
    float ax_ = vb[i0 * 3 + 0], ay_ = vb[i0 * 3 + 1], az_ = vb[i0 * 3 + 2];
    float bx_ = vb[i1 * 3 + 0], by_ = vb[i1 * 3 + 1], bz_ = vb[i1 * 3 + 2];
    float cx_ = vb[i2 * 3 + 0], cy_ = vb[i2 * 3 + 1], cz_ = vb[i2 * 3 + 2];
    float dx_ = vb[i3 * 3 + 0], dy_ = vb[i3 * 3 + 1], dz_ = vb[i3 * 3 + 2];

    float e1x = bx_ - ax_, e1y = by_ - ay_, e1z = bz_ - az_;
    float e2x = cx_ - ax_, e2y = cy_ - ay_, e2z = cz_ - az_;
    float e3x = dx_ - ax_, e3y = dy_ - ay_, e3z = dz_ - az_;

    // c23 = e2 x e3 ; l1 = p . c23 * iv
    float n1x = e2y * e3z - e2z * e3y;
    float n1y = e2z * e3x - e2x * e3z;
    float n1z = e2x * e3y - e2y * e3x;
    float vol6 = e1x * n1x + e1y * n1y + e1z * n1z;
    if (fabsf(vol6) <= 1e-12f) return;
    float iv = 1.0f / vol6;

    // c31 = e3 x e1 ; l2 = p . c31 * iv   (== (p x e3) . e1)
    float n2x = e3y * e1z - e3z * e1y;
    float n2y = e3z * e1x - e3x * e1z;
    float n2z = e3x * e1y - e3y * e1x;
    // c12 = e1 x e2 ; l3 = p . c12 * iv   (== (e2 x p) . e1)
    float n3x = e1y * e2z - e1z * e2y;
    float n3y = e1z * e2x - e1x * e2z;
    float n3z = e1x * e2y - e1y * e2x;

    float mnx = fminf(fminf(ax_, bx_), fminf(cx_, dx_));
    float mny = fminf(fminf(ay_, by_), fminf(cy_, dy_));
    float mnz = fminf(fminf(az_, bz_), fminf(cz_, dz_));
    int anx = (int)floorf(mnx * (float)R);
    int any_ = (int)floorf(mny * (float)R);
    int anz = (int)floorf(mnz * (float)R);

    int xs = max(anx, 0),  xe = min(anx + 4, R - 1);
    int ys = max(any_, 0), ye = min(any_ + 4, R - 1);
    int zs = max(anz, 0),  ze = min(anz + 4, R - 1);
    if (xs > xe || ys > ye || zs > ze) return;

    unsigned char* occ_b = g_occ + (size_t)b * R3;

    for (int z = zs; z <= ze; z++) {
        float pz = ((float)z + 0.5f) * INV_R - az_;
        for (int y = ys; y <= ye; y++) {
            float py = ((float)y + 0.5f) * INV_R - ay_;
            for (int x = xs; x <= xe; x++) {
                float px = ((float)x + 0.5f) * INV_R - ax_;
                float l1 = (px * n1x + py * n1y + pz * n1z) * iv;
                float l2 = (px * n2x + py * n2y + pz * n2z) * iv;
                float l3 = (px * n3x + py * n3y + pz * n3z) * iv;
                if (l1 >= 0.f && l2 >= 0.f && l3 >= 0.f && (l1 + l2 + l3) <= 1.0f)
                    occ_b[(z * R + y) * R + x] = 1;
            }
        }
    }
}

// ---------------------------------------------------------------------------
// 4) splat+finalize (fused): one block per 8^3 tile; each thread owns one
//    voxel, accumulates in registers over the tile's vertex list, then reads
//    occ and writes the 3 output channels directly. No global atomics.
// ---------------------------------------------------------------------------
__global__ __launch_bounds__(512)
void splat_final_kernel(const float* __restrict__ verts,
                        const float* __restrict__ code,
                        float* __restrict__ out) {
    int tile = blockIdx.x;                   // 0 .. NTILE-1
    int b  = tile >> 12;                     // / NTILE_B
    int tl = tile & (NTILE_B - 1);
    int x0 = (tl & 15) * TILE;
    int y0 = ((tl >> 4) & 15) * TILE;
    int z0 = (tl >> 8) * TILE;

    int tid = threadIdx.x;
    int X = x0 + (tid & 7);
    int Y = y0 + ((tid >> 3) & 7);
    int Z = z0 + (tid >> 6);

    float cx = ((float)X + 0.5f) * INV_R;
    float cy = ((float)Y + 0.5f) * INV_R;
    float cz = ((float)Z + 0.5f) * INV_R;

    float ar = 0.f, ag = 0.f, ab = 0.f, ws = EPS_W;

    int cnt = g_cnt[tile];
    if (cnt > CAP) cnt = CAP;
    const int* list = g_list + (size_t)tile * CAP;

    for (int j = 0; j < cnt; j++) {
        int s = list[j];
        const float* vp = verts + ((size_t)b * NV + s) * 3;
        float vx = vp[0], vy = vp[1], vz = vp[2];
        int bx = (int)floorf(vx * (float)R);
        int by = (int)floorf(vy * (float)R);
        int bz = (int)floorf(vz * (float)R);

        if (abs(X - bx) <= 3 && abs(Y - by) <= 3 && abs(Z - bz) <= 3) {
            float dx = cx - vx, dy = cy - vy, dz = cz - vz;
            float d2 = dx * dx + dy * dy + dz * dz;
            float w = __expf(-d2 * INV_2SIG2);
            const float* cp = code + ((size_t)b * NSURF + s) * 3;
            ar += w * cp[0];
            ag += w * cp[1];
            ab += w * cp[2];
            ws += w;
        }
    }

    int lin = (Z * R + Y) * R + X;
    float scale = g_occ[(size_t)b * R3 + lin] ? (1.0f / ws) : 0.0f;

    float* ob = out + (size_t)b * 3 * R3 + lin;
    ob[0 * R3] = ar * scale;
    ob[1 * R3] = ag * scale;
    ob[2 * R3] = ab * scale;
}

// ---------------------------------------------------------------------------
extern "C" void kernel_launch(void* const* d_in, const int* in_sizes, int n_in,
                              void* d_out, int out_size) {
    const float* verts = (const float*)d_in[0];   // smpl_vertices (B, NV, 3)
    const float* code  = (const float*)d_in[1];   // vertex_code   (B, NSURF, 3)
    // d_in[2] = face_indices: dead code in the reference, unused.
    const int*   tets  = (const int*)  d_in[3];   // tet_indices   (NT, 4)
    float*       out   = (float*)d_out;           // (B, 3, R, R, R)

    init_kernel       <<<(OCC_WORDS + 255) / 256, 256>>>();
    bin_kernel        <<<(BATCH * NSURF + 127) / 128, 128>>>(verts);
    tet_kernel        <<<(BATCH * NT + 127) / 128, 128>>>(verts, tets);
    splat_final_kernel<<<NTILE, 512>>>(verts, code, out);
}

// round 6
// speedup vs baseline: 1.5154x; 1.5154x over previous
#include <cuda_runtime.h>
#include <cstdint>

#define R      128
#define R2     (R * R)
#define R3     (R * R * R)
#define BATCH  2
#define NV     7700
#define NSURF  6890
#define NT     30000

#define SIGMA  0.05f
#define EPS_W  0.001f
#define INV_2SIG2 (1.0f / (2.0f * SIGMA * SIGMA))   // 200.0
#define INV_R  (1.0f / 128.0f)

// Tiling for the gather-splat kernel
#define TILE      8
#define TILES_AX  (R / TILE)                       // 16
#define NTILE_B   (TILES_AX * TILES_AX * TILES_AX) // 4096
#define NTILE     (BATCH * NTILE_B)                // 8192
#define CAP       96                               // max vertices per tile (mean ~13)

__device__ unsigned char g_occ[BATCH * R3];        // ~4.2 MB
__device__ int           g_cnt[NTILE];
__device__ int           g_list[NTILE * CAP];      // ~3 MB

// ---------------------------------------------------------------------------
// 1) init: occ = 0 (word-wide), tile counts = 0
// ---------------------------------------------------------------------------
#define OCC_WORDS (BATCH * R3 / 4)
__global__ void init_kernel() {
    int i = blockIdx.x * blockDim.x + threadIdx.x;
    if (i < OCC_WORDS) ((unsigned int*)g_occ)[i] = 0u;
    if (i < NTILE)     g_cnt[i] = 0;
}

// ---------------------------------------------------------------------------
// 2) bin: each surface vertex registers with every 8^3 tile its 7^3 box hits
// ---------------------------------------------------------------------------
__global__ void bin_kernel(const float* __restrict__ verts) {
    int t = blockIdx.x * blockDim.x + threadIdx.x;
    if (t >= BATCH * NSURF) return;
    int b = t / NSURF;
    int s = t - b * NSURF;

    const float* vp = verts + ((size_t)b * NV + s) * 3;
    int bx = (int)floorf(vp[0] * (float)R);
    int by = (int)floorf(vp[1] * (float)R);
    int bz = (int)floorf(vp[2] * (float)R);

    int txs = max(bx - 3, 0) >> 3, txe = min(bx + 3, R - 1) >> 3;
    int tys = max(by - 3, 0) >> 3, tye = min(by + 3, R - 1) >> 3;
    int tzs = max(bz - 3, 0) >> 3, tze = min(bz + 3, R - 1) >> 3;

    for (int tz = tzs; tz <= tze; tz++)
        for (int ty = tys; ty <= tye; ty++)
            for (int tx = txs; tx <= txe; tx++) {
                int tile = b * NTILE_B + (tz * TILES_AX + ty) * TILES_AX + tx;
                int pos = atomicAdd(&g_cnt[tile], 1);
                if (pos < CAP) g_list[tile * CAP + pos] = s;
            }
}

// ---------------------------------------------------------------------------
// 3) tet occupancy: one thread per (batch, tet, z-slice) for latency hiding
// ---------------------------------------------------------------------------
__global__ void tet_kernel(const float* __restrict__ verts,
                           const int*   __restrict__ tets) {
    int t = blockIdx.x * blockDim.x + threadIdx.x;
    if (t >= BATCH * NT * 5) return;
    int zi = t % 5;
    int tt = t / 5;
    int b  = tt / NT;
    int ti = tt - b * NT;

    int i0 = tets[ti * 4 + 0];
    int i1 = tets[ti * 4 + 1];
    int i2 = tets[ti * 4 + 2];
    int i3 = tets[ti * 4 + 3];

    const float* vb = verts + (size_t)b * NV * 3;
    float ax_ = vb[i0 * 3 + 0], ay_ = vb[i0 * 3 + 1], az_ = vb[i0 * 3 + 2];
    float bx_ = vb[i1 * 3 + 0], by_ = vb[i1 * 3 + 1], bz_ = vb[i1 * 3 + 2];
    float cx_ = vb[i2 * 3 + 0], cy_ = vb[i2 * 3 + 1], cz_ = vb[i2 * 3 + 2];
    float dx_ = vb[i3 * 3 + 0], dy_ = vb[i3 * 3 + 1], dz_ = vb[i3 * 3 + 2];

    float e1x = bx_ - ax_, e1y = by_ - ay_, e1z = bz_ - az_;
    float e2x = cx_ - ax_, e2y = cy_ - ay_, e2z = cz_ - az_;
    float e3x = dx_ - ax_, e3y = dy_ - ay_, e3z = dz_ - az_;

    float n1x = e2y * e3z - e2z * e3y;              // c23 = e2 x e3
    float n1y = e2z * e3x - e2x * e3z;
    float n1z = e2x * e3y - e2y * e3x;
    float vol6 = e1x * n1x + e1y * n1y + e1z * n1z;
    if (fabsf(vol6) <= 1e-12f) return;
    float iv = 1.0f / vol6;

    float n2x = e3y * e1z - e3z * e1y;              // c31 = e3 x e1
    float n2y = e3z * e1x - e3x * e1z;
    float n2z = e3x * e1y - e3y * e1x;
    float n3x = e1y * e2z - e1z * e2y;              // c12 = e1 x e2
    float n3y = e1z * e2x - e1x * e2z;
    float n3z = e1x * e2y - e1y * e2x;

    float mnx = fminf(fminf(ax_, bx_), fminf(cx_, dx_));
    float mny = fminf(fminf(ay_, by_), fminf(cy_, dy_));
    float mnz = fminf(fminf(az_, bz_), fminf(cz_, dz_));
    int anx = (int)floorf(mnx * (float)R);
    int any_ = (int)floorf(mny * (float)R);
    int anz = (int)floorf(mnz * (float)R);

    int z = anz + zi;
    if ((unsigned)z >= R) return;
    int xs = max(anx, 0),  xe = min(anx + 4, R - 1);
    int ys = max(any_, 0), ye = min(any_ + 4, R - 1);
    if (xs > xe || ys > ye) return;

    unsigned char* occ_b = g_occ + (size_t)b * R3;
    float pz = ((float)z + 0.5f) * INV_R - az_;

    for (int y = ys; y <= ye; y++) {
        float py = ((float)y + 0.5f) * INV_R - ay_;
        for (int x = xs; x <= xe; x++) {
            float px = ((float)x + 0.5f) * INV_R - ax_;
            float l1 = (px * n1x + py * n1y + pz * n1z) * iv;
            float l2 = (px * n2x + py * n2y + pz * n2z) * iv;
            float l3 = (px * n3x + py * n3y + pz * n3z) * iv;
            if (l1 >= 0.f && l2 >= 0.f && l3 >= 0.f && (l1 + l2 + l3) <= 1.0f)
                occ_b[(z * R + y) * R + x] = 1;
        }
    }
}

// ---------------------------------------------------------------------------
// 4) splat+finalize: per-vertex separable weight tables in shared (with 0s
//    outside the 7^3 box), then a ~10-instruction accumulate loop per voxel.
// ---------------------------------------------------------------------------
__global__ __launch_bounds__(512)
void splat_final_kernel(const float* __restrict__ verts,
                        const float* __restrict__ code,
                        float* __restrict__ out) {
    __shared__ float  swx[CAP * 8], swy[CAP * 8], swz[CAP * 8];
    __shared__ float4 scode[CAP];
    __shared__ float  spos[CAP * 3];
    __shared__ int    sbase[CAP * 3];

    int tile = blockIdx.x;                   // 0 .. NTILE-1
    int b  = tile >> 12;
    int tl = tile & (NTILE_B - 1);
    int x0 = (tl & 15) * TILE;
    int y0 = ((tl >> 4) & 15) * TILE;
    int z0 = (tl >> 8) * TILE;

    int tid = threadIdx.x;
    int cnt = g_cnt[tile];
    if (cnt > CAP) cnt = CAP;

    // Phase 1: load vertex data for this tile's list
    if (tid < cnt) {
        int s = g_list[(size_t)tile * CAP + tid];
        const float* vp = verts + ((size_t)b * NV + s) * 3;
        float vx = vp[0], vy = vp[1], vz = vp[2];
        spos[tid * 3 + 0] = vx;
        spos[tid * 3 + 1] = vy;
        spos[tid * 3 + 2] = vz;
        sbase[tid * 3 + 0] = (int)floorf(vx * (float)R);
        sbase[tid * 3 + 1] = (int)floorf(vy * (float)R);
        sbase[tid * 3 + 2] = (int)floorf(vz * (float)R);
        const float* cp = code + ((size_t)b * NSURF + s) * 3;
        scode[tid] = make_float4(cp[0], cp[1], cp[2], 1.0f);
    }
    __syncthreads();

    // Phase 2: fill separable weight tables (zero outside the |off|<=3 box)
    int nent = cnt * 24;
    for (int idx = tid; idx < nent; idx += 512) {
        int j = idx / 24;
        int k = idx - j * 24;
        int axis = k >> 3;                   // 0:x 1:y 2:z
        int o    = k & 7;                    // coordinate within tile
        int coord = (axis == 0 ? x0 : axis == 1 ? y0 : z0) + o;
        float vc  = spos[j * 3 + axis];
        int   bse = sbase[j * 3 + axis];
        float d   = ((float)coord + 0.5f) * INV_R - vc;
        float w   = (abs(coord - bse) <= 3) ? __expf(-d * d * INV_2SIG2) : 0.0f;
        if      (axis == 0) swx[j * 8 + o] = w;
        else if (axis == 1) swy[j * 8 + o] = w;
        else                swz[j * 8 + o] = w;
    }
    __syncthreads();

    // Phase 3: accumulate in registers
    int lx = tid & 7, ly = (tid >> 3) & 7, lz = tid >> 6;
    float ar = 0.f, ag = 0.f, ab = 0.f, ws = EPS_W;

    #pragma unroll 4
    for (int j = 0; j < cnt; j++) {
        float w = swx[j * 8 + lx] * swy[j * 8 + ly] * swz[j * 8 + lz];
        float4 c = scode[j];
        ar = fmaf(w, c.x, ar);
        ag = fmaf(w, c.y, ag);
        ab = fmaf(w, c.z, ab);
        ws += w;
    }

    int X = x0 + lx, Y = y0 + ly, Z = z0 + lz;
    int lin = (Z * R + Y) * R + X;
    float scale = g_occ[(size_t)b * R3 + lin] ? (1.0f / ws) : 0.0f;

    float* ob = out + (size_t)b * 3 * R3 + lin;
    ob[0 * R3] = ar * scale;
    ob[1 * R3] = ag * scale;
    ob[2 * R3] = ab * scale;
}

// ---------------------------------------------------------------------------
extern "C" void kernel_launch(void* const* d_in, const int* in_sizes, int n_in,
                              void* d_out, int out_size) {
    const float* verts = (const float*)d_in[0];   // smpl_vertices (B, NV, 3)
    const float* code  = (const float*)d_in[1];   // vertex_code   (B, NSURF, 3)
    // d_in[2] = face_indices: dead code in the reference, unused.
    const int*   tets  = (const int*)  d_in[3];   // tet_indices   (NT, 4)
    float*       out   = (float*)d_out;           // (B, 3, R, R, R)

    init_kernel       <<<(OCC_WORDS + 255) / 256, 256>>>();
    bin_kernel        <<<(BATCH * NSURF + 127) / 128, 128>>>(verts);
    tet_kernel        <<<(BATCH * NT * 5 + 255) / 256, 256>>>(verts, tets);
    splat_final_kernel<<<NTILE, 512>>>(verts, code, out);
}

// round 7
// speedup vs baseline: 1.5336x; 1.0120x over previous
#include <cuda_runtime.h>
#include <cstdint>

#define R      128
#define R2     (R * R)
#define R3     (R * R * R)
#define BATCH  2
#define NV     7700
#define NSURF  6890
#define NT     30000

#define SIGMA  0.05f
#define EPS_W  0.001f
#define INV_2SIG2 (1.0f / (2.0f * SIGMA * SIGMA))   // 200.0
#define INV_R  (1.0f / 128.0f)

// Tiling for the gather-splat kernel
#define TILE      8
#define TILES_AX  (R / TILE)                       // 16
#define NTILE_B   (TILES_AX * TILES_AX * TILES_AX) // 4096
#define NTILE     (BATCH * NTILE_B)                // 8192
#define CAP       48                               // max vertices per tile (Poisson λ≈9)
#define TPB       512
#define TILES_PER_BLK 4                            // 128 threads per tile

__device__ unsigned char g_occ[BATCH * R3];        // ~4.2 MB
__device__ int           g_cnt[NTILE];
__device__ int           g_list[NTILE * CAP];

// ---------------------------------------------------------------------------
// 1) bin: each surface vertex registers with every 8^3 tile its 7^3 box hits
// ---------------------------------------------------------------------------
__global__ void bin_kernel(const float* __restrict__ verts) {
    int t = blockIdx.x * blockDim.x + threadIdx.x;
    if (t >= BATCH * NSURF) return;
    int b = t / NSURF;
    int s = t - b * NSURF;

    const float* vp = verts + ((size_t)b * NV + s) * 3;
    int bx = (int)floorf(vp[0] * (float)R);
    int by = (int)floorf(vp[1] * (float)R);
    int bz = (int)floorf(vp[2] * (float)R);

    int txs = max(bx - 3, 0) >> 3, txe = min(bx + 3, R - 1) >> 3;
    int tys = max(by - 3, 0) >> 3, tye = min(by + 3, R - 1) >> 3;
    int tzs = max(bz - 3, 0) >> 3, tze = min(bz + 3, R - 1) >> 3;

    for (int tz = tzs; tz <= tze; tz++)
        for (int ty = tys; ty <= tye; ty++)
            for (int tx = txs; tx <= txe; tx++) {
                int tile = b * NTILE_B + (tz * TILES_AX + ty) * TILES_AX + tx;
                int pos = atomicAdd(&g_cnt[tile], 1);
                if (pos < CAP) g_list[tile * CAP + pos] = s;
            }
}

// ---------------------------------------------------------------------------
// 2) tet occupancy: one thread per (batch, tet, z-slice)
// ---------------------------------------------------------------------------
__global__ void tet_kernel(const float* __restrict__ verts,
                           const int*   __restrict__ tets) {
    int t = blockIdx.x * blockDim.x + threadIdx.x;
    if (t >= BATCH * NT * 5) return;
    int zi = t % 5;
    int tt = t / 5;
    int b  = tt / NT;
    int ti = tt - b * NT;

    int4 idx4 = ((const int4*)tets)[ti];

    const float* vb = verts + (size_t)b * NV * 3;
    float ax_ = vb[idx4.x * 3 + 0], ay_ = vb[idx4.x * 3 + 1], az_ = vb[idx4.x * 3 + 2];
    float bx_ = vb[idx4.y * 3 + 0], by_ = vb[idx4.y * 3 + 1], bz_ = vb[idx4.y * 3 + 2];
    float cx_ = vb[idx4.z * 3 + 0], cy_ = vb[idx4.z * 3 + 1], cz_ = vb[idx4.z * 3 + 2];
    float dx_ = vb[idx4.w * 3 + 0], dy_ = vb[idx4.w * 3 + 1], dz_ = vb[idx4.w * 3 + 2];

    float e1x = bx_ - ax_, e1y = by_ - ay_, e1z = bz_ - az_;
    float e2x = cx_ - ax_, e2y = cy_ - ay_, e2z = cz_ - az_;
    float e3x = dx_ - ax_, e3y = dy_ - ay_, e3z = dz_ - az_;

    float n1x = e2y * e3z - e2z * e3y;              // c23 = e2 x e3
    float n1y = e2z * e3x - e2x * e3z;
    float n1z = e2x * e3y - e2y * e3x;
    float vol6 = e1x * n1x + e1y * n1y + e1z * n1z;
    if (fabsf(vol6) <= 1e-12f) return;
    float iv = 1.0f / vol6;

    float n2x = e3y * e1z - e3z * e1y;              // c31 = e3 x e1
    float n2y = e3z * e1x - e3x * e1z;
    float n2z = e3x * e1y - e3y * e1x;
    float n3x = e1y * e2z - e1z * e2y;              // c12 = e1 x e2
    float n3y = e1z * e2x - e1x * e2z;
    float n3z = e1x * e2y - e1y * e2x;

    float mnx = fminf(fminf(ax_, bx_), fminf(cx_, dx_));
    float mny = fminf(fminf(ay_, by_), fminf(cy_, dy_));
    float mnz = fminf(fminf(az_, bz_), fminf(cz_, dz_));
    int anx = (int)floorf(mnx * (float)R);
    int any_ = (int)floorf(mny * (float)R);
    int anz = (int)floorf(mnz * (float)R);

    int z = anz + zi;
    if ((unsigned)z >= R) return;
    int xs = max(anx, 0),  xe = min(anx + 4, R - 1);
    int ys = max(any_, 0), ye = min(any_ + 4, R - 1);
    if (xs > xe || ys > ye) return;

    unsigned char* occ_b = g_occ + (size_t)b * R3;
    float pz = ((float)z + 0.5f) * INV_R - az_;

    for (int y = ys; y <= ye; y++) {
        float py = ((float)y + 0.5f) * INV_R - ay_;
        for (int x = xs; x <= xe; x++) {
            float px = ((float)x + 0.5f) * INV_R - ax_;
            float l1 = (px * n1x + py * n1y + pz * n1z) * iv;
            float l2 = (px * n2x + py * n2y + pz * n2z) * iv;
            float l3 = (px * n3x + py * n3y + pz * n3z) * iv;
            if (l1 >= 0.f && l2 >= 0.f && l3 >= 0.f && (l1 + l2 + l3) <= 1.0f)
                occ_b[(z * R + y) * R + x] = 1;
        }
    }
}

// ---------------------------------------------------------------------------
// 3) splat+finalize: 4 tiles per block, 128 threads per tile, each thread
//    owns a half x-row (4 voxels). Separable weight tables in shared.
// ---------------------------------------------------------------------------
__global__ __launch_bounds__(TPB)
void splat_final_kernel(const float* __restrict__ verts,
                        const float* __restrict__ code,
                        float* __restrict__ out) {
    __shared__ float  swx[TILES_PER_BLK][CAP * 8];
    __shared__ float  swy[TILES_PER_BLK][CAP * 8];
    __shared__ float  swz[TILES_PER_BLK][CAP * 8];
    __shared__ float4 scode[TILES_PER_BLK][CAP];

    int g    = threadIdx.x >> 7;                 // tile group within block
    int t    = threadIdx.x & 127;                // thread within group
    int tile = blockIdx.x * TILES_PER_BLK + g;   // 0 .. NTILE-1
    int b  = tile >> 12;
    int tl = tile & (NTILE_B - 1);
    int x0 = (tl & 15) * TILE;
    int y0 = ((tl >> 4) & 15) * TILE;
    int z0 = (tl >> 8) * TILE;

    int cnt = g_cnt[tile];
    if (cnt > CAP) cnt = CAP;

    // Phase 1: each listed vertex computes its own 24 separable weights
    if (t < cnt) {
        int s = g_list[tile * CAP + t];
        const float* vp = verts + ((size_t)b * NV + s) * 3;
        float vx = vp[0], vy = vp[1], vz = vp[2];
        int bx = (int)floorf(vx * (float)R);
        int by = (int)floorf(vy * (float)R);
        int bz = (int)floorf(vz * (float)R);
        const float* cp = code + ((size_t)b * NSURF + s) * 3;
        scode[g][t] = make_float4(cp[0], cp[1], cp[2], 0.0f);

        #pragma unroll
        for (int o = 0; o < 8; o++) {
            int cx_i = x0 + o, cy_i = y0 + o, cz_i = z0 + o;
            float dxv = ((float)cx_i + 0.5f) * INV_R - vx;
            float dyv = ((float)cy_i + 0.5f) * INV_R - vy;
            float dzv = ((float)cz_i + 0.5f) * INV_R - vz;
            swx[g][t * 8 + o] = (abs(cx_i - bx) <= 3) ? __expf(-dxv * dxv * INV_2SIG2) : 0.0f;
            swy[g][t * 8 + o] = (abs(cy_i - by) <= 3) ? __expf(-dyv * dyv * INV_2SIG2) : 0.0f;
            swz[g][t * 8 + o] = (abs(cz_i - bz) <= 3) ? __expf(-dzv * dzv * INV_2SIG2) : 0.0f;
        }
    }
    __syncthreads();

    // Phase 2: accumulate 4 voxels (half x-row) per thread in registers
    int xh = t & 1;                  // which x half: 0 -> x0..x0+3, 1 -> x0+4..x0+7
    int ly = (t >> 1) & 7;
    int lz = t >> 4;

    float4 ar = make_float4(0.f, 0.f, 0.f, 0.f);
    float4 ag = make_float4(0.f, 0.f, 0.f, 0.f);
    float4 ab = make_float4(0.f, 0.f, 0.f, 0.f);
    float4 ws = make_float4(EPS_W, EPS_W, EPS_W, EPS_W);

    for (int j = 0; j < cnt; j++) {
        float wyz = swy[g][j * 8 + ly] * swz[g][j * 8 + lz];
        float4 wx = *(const float4*)&swx[g][j * 8 + xh * 4];
        float4 c  = scode[g][j];
        float w0 = wx.x * wyz, w1 = wx.y * wyz, w2 = wx.z * wyz, w3 = wx.w * wyz;
        ar.x = fmaf(w0, c.x, ar.x); ar.y = fmaf(w1, c.x, ar.y);
        ar.z = fmaf(w2, c.x, ar.z); ar.w = fmaf(w3, c.x, ar.w);
        ag.x = fmaf(w0, c.y, ag.x); ag.y = fmaf(w1, c.y, ag.y);
        ag.z = fmaf(w2, c.y, ag.z); ag.w = fmaf(w3, c.y, ag.w);
        ab.x = fmaf(w0, c.z, ab.x); ab.y = fmaf(w1, c.z, ab.y);
        ab.z = fmaf(w2, c.z, ab.z); ab.w = fmaf(w3, c.z, ab.w);
        ws.x += w0; ws.y += w1; ws.z += w2; ws.w += w3;
    }

    // Phase 3: finalize with occupancy, vectorized stores
    int X = x0 + xh * 4;
    int Y = y0 + ly;
    int Z = z0 + lz;
    int lin = (Z * R + Y) * R + X;

    unsigned int occ4 = *(const unsigned int*)&g_occ[(size_t)b * R3 + lin];
    float s0 = (occ4 & 0x000000FFu) ? (1.0f / ws.x) : 0.0f;
    float s1 = (occ4 & 0x0000FF00u) ? (1.0f / ws.y) : 0.0f;
    float s2 = (occ4 & 0x00FF0000u) ? (1.0f / ws.z) : 0.0f;
    float s3 = (occ4 & 0xFF000000u) ? (1.0f / ws.w) : 0.0f;

    float* ob = out + (size_t)b * 3 * R3 + lin;
    *(float4*)&ob[0 * R3] = make_float4(ar.x * s0, ar.y * s1, ar.z * s2, ar.w * s3);
    *(float4*)&ob[1 * R3] = make_float4(ag.x * s0, ag.y * s1, ag.z * s2, ag.w * s3);
    *(float4*)&ob[2 * R3] = make_float4(ab.x * s0, ab.y * s1, ab.z * s2, ab.w * s3);
}

// ---------------------------------------------------------------------------
extern "C" void kernel_launch(void* const* d_in, const int* in_sizes, int n_in,
                              void* d_out, int out_size) {
    const float* verts = (const float*)d_in[0];   // smpl_vertices (B, NV, 3)
    const float* code  = (const float*)d_in[1];   // vertex_code   (B, NSURF, 3)
    // d_in[2] = face_indices: dead code in the reference, unused.
    const int*   tets  = (const int*)  d_in[3];   // tet_indices   (NT, 4)
    float*       out   = (float*)d_out;           // (B, 3, R, R, R)

    void* occ_ptr = nullptr;
    void* cnt_ptr = nullptr;
    cudaGetSymbolAddress(&occ_ptr, g_occ);
    cudaGetSymbolAddress(&cnt_ptr, g_cnt);
    cudaMemsetAsync(occ_ptr, 0, (size_t)BATCH * R3, 0);
    cudaMemsetAsync(cnt_ptr, 0, (size_t)NTILE * sizeof(int), 0);

    bin_kernel        <<<(BATCH * NSURF + 127) / 128, 128>>>(verts);
    tet_kernel        <<<(BATCH * NT * 5 + 255) / 256, 256>>>(verts, tets);
    splat_final_kernel<<<NTILE / TILES_PER_BLK, TPB>>>(verts, code, out);
}